// round 16
// baseline (speedup 1.0000x reference)
#include <cuda_runtime.h>
#include <cuda_fp16.h>
#include <cstdint>

#define B_  2
#define H_  12
#define S_  2048
#define D_  64
#define BM  64
#define BN  64
#define NT  (S_ / BN)
#define NELEM (B_ * H_ * S_ * D_)

// ---- preconverted, pre-swizzled tile buffers (8 KB per 64-row tile) ----
__device__ __half g_Kh[NELEM];
__device__ __half g_Vh[NELEM];

__device__ __forceinline__ float ex2f(float x) {
    float y;
    asm("ex2.approx.ftz.f32 %0, %1;" : "=f"(y) : "f"(x));
    return y;
}

__device__ __forceinline__ uint32_t pack2(__half a, __half b) {
    __half2 h = __halves2half2(a, b);
    return *reinterpret_cast<uint32_t*>(&h);
}

__device__ __forceinline__ uint32_t s2u(const void* p) {
    uint32_t a;
    asm("{ .reg .u64 t; cvta.to.shared.u64 t, %1; cvt.u32.u64 %0, t; }" : "=r"(a) : "l"(p));
    return a;
}

__device__ __forceinline__ uint32_t swoff(int row, int byteoff) {
    uint32_t blk = ((uint32_t)byteoff >> 4) ^ ((uint32_t)row & 7);
    return (uint32_t)row * 128u + (blk << 4) + ((uint32_t)byteoff & 15u);
}

__device__ __forceinline__ uint32_t swaddr(uint32_t base, int row, int byteoff) {
    return base + swoff(row, byteoff);
}

__device__ __forceinline__ void mma16816(float d[4], const uint32_t a[4],
                                         uint32_t b0, uint32_t b1) {
    asm volatile(
        "mma.sync.aligned.m16n8k16.row.col.f32.f16.f16.f32 "
        "{%0,%1,%2,%3}, {%4,%5,%6,%7}, {%8,%9}, {%0,%1,%2,%3};\n"
        : "+f"(d[0]), "+f"(d[1]), "+f"(d[2]), "+f"(d[3])
        : "r"(a[0]), "r"(a[1]), "r"(a[2]), "r"(a[3]), "r"(b0), "r"(b1));
}

__device__ __forceinline__ void ldm_x4(uint32_t r[4], uint32_t addr) {
    asm volatile("ldmatrix.sync.aligned.m8n8.x4.shared.b16 {%0,%1,%2,%3}, [%4];"
                 : "=r"(r[0]), "=r"(r[1]), "=r"(r[2]), "=r"(r[3]) : "r"(addr));
}

__device__ __forceinline__ void ldm_x4_t(uint32_t r[4], uint32_t addr) {
    asm volatile("ldmatrix.sync.aligned.m8n8.x4.trans.shared.b16 {%0,%1,%2,%3}, [%4];"
                 : "=r"(r[0]), "=r"(r[1]), "=r"(r[2]), "=r"(r[3]) : "r"(addr));
}

__device__ __forceinline__ void cp16(uint32_t smem, const void* g) {
    asm volatile("cp.async.cg.shared.global [%0], [%1], 16;"
                 :: "r"(smem), "l"(__cvta_generic_to_global(g)) : "memory");
}
#define CP_COMMIT() asm volatile("cp.async.commit_group;" ::: "memory")
#define CP_WAIT0()  asm volatile("cp.async.wait_group 0;" ::: "memory")

// A-fragment (Q) ldmatrix address
__device__ __forceinline__ uint32_t qaddr(uint32_t base, int m0, int kt, int lane) {
    int row  = m0 + (lane & 7) + ((lane >> 3) & 1) * 8;
    int byte = kt * 32 + (lane >> 4) * 16;
    return swaddr(base, row, byte);
}

// B-fragment (K) ldmatrix address
__device__ __forceinline__ uint32_t kaddr(uint32_t base, int nbase, int kbase, int lane) {
    int r = lane & 7;
    int n = nbase + ((lane >> 4) << 3) + r;
    int kcol = kbase + ((lane >> 3) & 1) * 8;
    return swaddr(base, n, kcol * 2);
}

// B-fragment (V, trans) address
__device__ __forceinline__ uint32_t vaddr(uint32_t base, int nbase, int dbase, int lane) {
    int r = lane & 7;
    int n = nbase + ((lane >> 3) & 1) * 8 + r;
    int d = dbase + ((lane >> 4) << 3);
    return swaddr(base, n, d * 2);
}

// ================= precompute: K,V fp32 -> fp16, tile-swizzled ===============
__global__ __launch_bounds__(256)
void conv_kernel(const float* __restrict__ k, const float* __restrict__ v)
{
    size_t idx4 = (size_t)blockIdx.x * blockDim.x + threadIdx.x;
    size_t e = idx4 * 4;
    if (e >= NELEM) return;
    int d      = (int)(e & 63);
    int s      = (int)((e >> 6) & (S_ - 1));
    size_t bh  = e >> 17;
    int jb     = s >> 6;
    int row    = s & 63;
    size_t tb  = ((bh * NT) + jb) * 8192;
    uint32_t o = swoff(row, d * 2);

    float4 kx = *reinterpret_cast<const float4*>(k + e);
    float4 vx = *reinterpret_cast<const float4*>(v + e);

    *reinterpret_cast<uint2*>((char*)g_Kh + tb + o) =
        make_uint2(pack2(__float2half_rn(kx.x), __float2half_rn(kx.y)),
                   pack2(__float2half_rn(kx.z), __float2half_rn(kx.w)));
    *reinterpret_cast<uint2*>((char*)g_Vh + tb + o) =
        make_uint2(pack2(__float2half_rn(vx.x), __float2half_rn(vx.y)),
                   pack2(__float2half_rn(vx.z), __float2half_rn(vx.w)));
}

// ================= main attention kernel =====================================
struct Smem {
    __half Qh[BM][64];      // 8 KB  static
    __half Ql[BM][64];      // 8 KB  static
    __half Kh[2][BN][64];   // 16 KB double
    __half Vr[2][BN][64];   // 16 KB double
};                          // 48 KB -> 3 CTAs/SM

#define OEX_LD 68

__global__ __launch_bounds__(128, 3)
void fa_kernel(const float* __restrict__ q, const float* __restrict__ mask,
               float* __restrict__ out)
{
    __shared__ Smem sm;

    const int bh   = blockIdx.x;
    const int qb   = blockIdx.y;
    const int b    = bh / H_;
    const int tid  = threadIdx.x;
    const int warp = tid >> 5;
    const int lane = tid & 31;
    const int c    = warp & 1;        // kv-col half
    const int r    = warp >> 1;       // q-row half
    const int g    = lane >> 2;
    const int t    = lane & 3;

    const uint32_t qhb = s2u(&sm.Qh[0][0]);
    const uint32_t qlb = s2u(&sm.Ql[0][0]);
    const uint32_t khb[2] = { s2u(&sm.Kh[0][0][0]), s2u(&sm.Kh[1][0][0]) };
    const uint32_t vrb[2] = { s2u(&sm.Vr[0][0][0]), s2u(&sm.Vr[1][0][0]) };

    const int row0 = qb * BM + r * 32;

    const char* gKh = (const char*)g_Kh + (size_t)bh * NT * 8192;
    const char* gVh = (const char*)g_Vh + (size_t)bh * NT * 8192;

    // cp.async one 16 KB tile (Kh,V) into buffer buf
    auto cp_tile = [&](int jb, int buf) {
        size_t tb = (size_t)jb * 8192;
#pragma unroll
        for (int i = 0; i < 4; ++i) {
            uint32_t o = (uint32_t)(tid + i * 128) * 16;
            cp16(khb[buf] + o, gKh + tb + o);
            cp16(vrb[buf] + o, gVh + tb + o);
        }
    };

    cp_tile(0, 0);
    CP_COMMIT();

    // ---- Q -> smem hi/lo fp16 (once, overlaps the first cp.async) ----
    {
        const int ld_row = tid >> 4;
        const int ld_c4  = (tid & 15) * 4;
        const float* qp = q + ((size_t)bh * S_ + qb * BM) * D_;
#pragma unroll
        for (int i = 0; i < 8; ++i) {
            int row = ld_row + i * 8;
            float4 x = *reinterpret_cast<const float4*>(qp + row * D_ + ld_c4);
            __half h0 = __float2half_rn(x.x), h1 = __float2half_rn(x.y);
            __half h2 = __float2half_rn(x.z), h3 = __float2half_rn(x.w);
            __half l0 = __float2half_rn(x.x - __half2float(h0));
            __half l1 = __float2half_rn(x.y - __half2float(h1));
            __half l2 = __float2half_rn(x.z - __half2float(h2));
            __half l3 = __float2half_rn(x.w - __half2float(h3));
            uint2 hv = make_uint2(pack2(h0, h1), pack2(h2, h3));
            uint2 lv = make_uint2(pack2(l0, l1), pack2(l2, l3));
            asm volatile("st.shared.v2.u32 [%0], {%1,%2};"
                         :: "r"(swaddr(qhb, row, ld_c4 * 2)), "r"(hv.x), "r"(hv.y));
            asm volatile("st.shared.v2.u32 [%0], {%1,%2};"
                         :: "r"(swaddr(qlb, row, ld_c4 * 2)), "r"(lv.x), "r"(lv.y));
        }
    }

    float oA[2][8][4];
#pragma unroll
    for (int mt = 0; mt < 2; ++mt)
#pragma unroll
        for (int jd = 0; jd < 8; ++jd)
#pragma unroll
            for (int i = 0; i < 4; ++i) oA[mt][jd][i] = 0.f;

    float m_run[2][2] = { {-1e30f, -1e30f}, {-1e30f, -1e30f} };
    float l_run[2][2] = { {0.f, 0.f}, {0.f, 0.f} };

    const float* mbase = mask + (size_t)b * S_ * S_
                       + (size_t)(row0 + g) * S_ + c * 32 + 2 * t;

    const float L2E = 1.4426950408889634f;

    CP_WAIT0();
    __syncthreads();

    for (int jb = 0; jb < NT; ++jb) {
        const int buf = jb & 1;

        // issue next tile's copies first — overlap with this tile's math
        if (jb + 1 < NT) { cp_tile(jb + 1, buf ^ 1); CP_COMMIT(); }

        float sA[2][4][4];
#pragma unroll
        for (int mt = 0; mt < 2; ++mt)
#pragma unroll
            for (int j8 = 0; j8 < 4; ++j8)
#pragma unroll
                for (int i = 0; i < 4; ++i) sA[mt][j8][i] = 0.f;

        // ---- S = Q K^T : 2-term fp16 split (qh*kh + ql*kh) ----
#pragma unroll
        for (int kt = 0; kt < 4; ++kt) {
            uint32_t ah[2][4], al[2][4], bh0[8];
#pragma unroll
            for (int mt = 0; mt < 2; ++mt) {
                ldm_x4(ah[mt], qaddr(qhb, r * 32 + mt * 16, kt, lane));
                ldm_x4(al[mt], qaddr(qlb, r * 32 + mt * 16, kt, lane));
            }
#pragma unroll
            for (int nb = 0; nb < 2; ++nb)
                ldm_x4(&bh0[nb * 4], kaddr(khb[buf], c * 32 + nb * 16, kt * 16, lane));
#pragma unroll
            for (int mt = 0; mt < 2; ++mt)
#pragma unroll
                for (int j8 = 0; j8 < 4; ++j8) {
                    int off = (j8 >> 1) * 4 + (j8 & 1) * 2;
                    mma16816(sA[mt][j8], ah[mt], bh0[off], bh0[off + 1]);
                    mma16816(sA[mt][j8], al[mt], bh0[off], bh0[off + 1]);
                }
        }

        // ---- additive mask (fp32, L2-resident) ----
        const float* mp = mbase + (size_t)jb * BN;
#pragma unroll
        for (int mt = 0; mt < 2; ++mt)
#pragma unroll
            for (int rr = 0; rr < 2; ++rr) {
                const float* mq = mp + (size_t)(mt * 16 + rr * 8) * S_;
#pragma unroll
                for (int j8 = 0; j8 < 4; ++j8) {
                    float2 mv = *reinterpret_cast<const float2*>(mq + j8 * 8);
                    sA[mt][j8][rr * 2 + 0] += mv.x;
                    sA[mt][j8][rr * 2 + 1] += mv.y;
                }
            }

        // ---- row max + alpha + O rescale (needs all scores; cheap) ----
        float mn[2][2], rs[2][2];
#pragma unroll
        for (int mt = 0; mt < 2; ++mt) {
            float rm0 = -1e30f, rm1 = -1e30f;
#pragma unroll
            for (int j8 = 0; j8 < 4; ++j8) {
                rm0 = fmaxf(rm0, fmaxf(sA[mt][j8][0], sA[mt][j8][1]));
                rm1 = fmaxf(rm1, fmaxf(sA[mt][j8][2], sA[mt][j8][3]));
            }
            rm0 = fmaxf(rm0, __shfl_xor_sync(0xffffffffu, rm0, 1));
            rm0 = fmaxf(rm0, __shfl_xor_sync(0xffffffffu, rm0, 2));
            rm1 = fmaxf(rm1, __shfl_xor_sync(0xffffffffu, rm1, 1));
            rm1 = fmaxf(rm1, __shfl_xor_sync(0xffffffffu, rm1, 2));

            mn[mt][0] = fmaxf(m_run[mt][0], rm0);
            mn[mt][1] = fmaxf(m_run[mt][1], rm1);
            float al0 = ex2f((m_run[mt][0] - mn[mt][0]) * L2E);
            float al1 = ex2f((m_run[mt][1] - mn[mt][1]) * L2E);
            m_run[mt][0] = mn[mt][0]; m_run[mt][1] = mn[mt][1];
            l_run[mt][0] *= al0; l_run[mt][1] *= al1;
            rs[mt][0] = 0.f; rs[mt][1] = 0.f;
#pragma unroll
            for (int jd = 0; jd < 8; ++jd) {
                oA[mt][jd][0] *= al0; oA[mt][jd][1] *= al0;
                oA[mt][jd][2] *= al1; oA[mt][jd][3] *= al1;
            }
        }

        // ---- interleaved: exp half -> PV half (ks = 0, 1) ----
#pragma unroll
        for (int ks = 0; ks < 2; ++ks) {
            // V fragments for this half first (no dependency on softmax)
            uint32_t bv[16];
#pragma unroll
            for (int db = 0; db < 4; ++db)
                ldm_x4_t(&bv[db * 4], vaddr(vrb[buf], c * 32 + ks * 16, db * 16, lane));

            // exp for score groups j8 = 2*ks, 2*ks+1
            uint32_t Pa[2][4];
#pragma unroll
            for (int mt = 0; mt < 2; ++mt)
#pragma unroll
                for (int jj = 0; jj < 2; ++jj) {
                    int j8 = ks * 2 + jj;
                    float p0 = ex2f((sA[mt][j8][0] - mn[mt][0]) * L2E);
                    float p1 = ex2f((sA[mt][j8][1] - mn[mt][0]) * L2E);
                    float p2 = ex2f((sA[mt][j8][2] - mn[mt][1]) * L2E);
                    float p3 = ex2f((sA[mt][j8][3] - mn[mt][1]) * L2E);
                    rs[mt][0] += p0 + p1;
                    rs[mt][1] += p2 + p3;
                    Pa[mt][jj * 2 + 0] = pack2(__float2half_rn(p0), __float2half_rn(p1));
                    Pa[mt][jj * 2 + 1] = pack2(__float2half_rn(p2), __float2half_rn(p3));
                }

            // PV for this half
#pragma unroll
            for (int mt = 0; mt < 2; ++mt)
#pragma unroll
                for (int jd = 0; jd < 8; ++jd) {
                    int off = (jd >> 1) * 4 + (jd & 1) * 2;
                    mma16816(oA[mt][jd], Pa[mt], bv[off], bv[off + 1]);
                }
        }

        // ---- fold partial sums into l_run ----
#pragma unroll
        for (int mt = 0; mt < 2; ++mt) {
            float rs0 = rs[mt][0], rs1 = rs[mt][1];
            rs0 += __shfl_xor_sync(0xffffffffu, rs0, 1);
            rs0 += __shfl_xor_sync(0xffffffffu, rs0, 2);
            rs1 += __shfl_xor_sync(0xffffffffu, rs1, 1);
            rs1 += __shfl_xor_sync(0xffffffffu, rs1, 2);
            l_run[mt][0] += rs0;
            l_run[mt][1] += rs1;
        }

        CP_WAIT0();
        __syncthreads();
    }

    // ---- epilogue: merge the two c-halves ----
    float* Oex = reinterpret_cast<float*>(&sm);          // [64][OEX_LD]
    float* Mex = Oex + 64 * OEX_LD;
    float* Lex = Mex + 64;

    if (c == 1) {
#pragma unroll
        for (int mt = 0; mt < 2; ++mt) {
#pragma unroll
            for (int rr = 0; rr < 2; ++rr) {
                int row_l = r * 32 + mt * 16 + rr * 8 + g;
#pragma unroll
                for (int jd = 0; jd < 8; ++jd) {
                    Oex[row_l * OEX_LD + jd * 8 + 2 * t]     = oA[mt][jd][rr * 2 + 0];
                    Oex[row_l * OEX_LD + jd * 8 + 2 * t + 1] = oA[mt][jd][rr * 2 + 1];
                }
            }
            if (t == 0) {
                int rl0 = r * 32 + mt * 16 + g;
                Mex[rl0]     = m_run[mt][0];  Lex[rl0]     = l_run[mt][0];
                Mex[rl0 + 8] = m_run[mt][1];  Lex[rl0 + 8] = l_run[mt][1];
            }
        }
    }
    __syncthreads();

    if (c == 0) {
#pragma unroll
        for (int mt = 0; mt < 2; ++mt) {
#pragma unroll
            for (int rr = 0; rr < 2; ++rr) {
                int row_l = r * 32 + mt * 16 + rr * 8 + g;
                float m0 = m_run[mt][rr], l0 = l_run[mt][rr];
                float m1 = Mex[row_l],    l1 = Lex[row_l];
                float m  = fmaxf(m0, m1);
                float s0 = ex2f((m0 - m) * L2E);
                float s1 = ex2f((m1 - m) * L2E);
                float inv = 1.f / (l0 * s0 + l1 * s1);
                float a0 = s0 * inv, a1 = s1 * inv;

                float* op = out + ((size_t)bh * S_ + qb * BM + row_l) * D_;
#pragma unroll
                for (int jd = 0; jd < 8; ++jd) {
                    float2 w;
                    w.x = oA[mt][jd][rr * 2 + 0] * a0 + Oex[row_l * OEX_LD + jd * 8 + 2 * t] * a1;
                    w.y = oA[mt][jd][rr * 2 + 1] * a0 + Oex[row_l * OEX_LD + jd * 8 + 2 * t + 1] * a1;
                    *reinterpret_cast<float2*>(op + jd * 8 + 2 * t) = w;
                }
            }
        }
    }
}

extern "C" void kernel_launch(void* const* d_in, const int* in_sizes, int n_in,
                              void* d_out, int out_size) {
    (void)in_sizes; (void)n_in; (void)out_size;
    const float* q    = (const float*)d_in[0];
    const float* k    = (const float*)d_in[1];
    const float* v    = (const float*)d_in[2];
    const float* mask = (const float*)d_in[3];

    conv_kernel<<<NELEM / 4 / 256, 256>>>(k, v);
    dim3 grid(B_ * H_, S_ / BM);
    fa_kernel<<<grid, 128>>>(q, mask, (float*)d_out);
}

// round 17
// speedup vs baseline: 1.4963x; 1.4963x over previous
#include <cuda_runtime.h>
#include <cuda_fp16.h>
#include <cstdint>

#define B_  2
#define H_  12
#define S_  2048
#define D_  64
#define BM  64
#define BN  64
#define NT  (S_ / BN)
#define NELEM (B_ * H_ * S_ * D_)

// ---- preconverted, pre-swizzled tile buffers (8 KB per 64-row tile) ----
__device__ __half g_Kh[NELEM];
__device__ __half g_Vh[NELEM];

__device__ __forceinline__ float ex2f(float x) {
    float y;
    asm("ex2.approx.ftz.f32 %0, %1;" : "=f"(y) : "f"(x));
    return y;
}

__device__ __forceinline__ uint32_t pack2(__half a, __half b) {
    __half2 h = __halves2half2(a, b);
    return *reinterpret_cast<uint32_t*>(&h);
}

__device__ __forceinline__ uint32_t s2u(const void* p) {
    uint32_t a;
    asm("{ .reg .u64 t; cvta.to.shared.u64 t, %1; cvt.u32.u64 %0, t; }" : "=r"(a) : "l"(p));
    return a;
}

__device__ __forceinline__ uint32_t swoff(int row, int byteoff) {
    uint32_t blk = ((uint32_t)byteoff >> 4) ^ ((uint32_t)row & 7);
    return (uint32_t)row * 128u + (blk << 4) + ((uint32_t)byteoff & 15u);
}

__device__ __forceinline__ uint32_t swaddr(uint32_t base, int row, int byteoff) {
    return base + swoff(row, byteoff);
}

__device__ __forceinline__ void mma16816(float d[4], const uint32_t a[4],
                                         uint32_t b0, uint32_t b1) {
    asm volatile(
        "mma.sync.aligned.m16n8k16.row.col.f32.f16.f16.f32 "
        "{%0,%1,%2,%3}, {%4,%5,%6,%7}, {%8,%9}, {%0,%1,%2,%3};\n"
        : "+f"(d[0]), "+f"(d[1]), "+f"(d[2]), "+f"(d[3])
        : "r"(a[0]), "r"(a[1]), "r"(a[2]), "r"(a[3]), "r"(b0), "r"(b1));
}

__device__ __forceinline__ void ldm_x4(uint32_t r[4], uint32_t addr) {
    asm volatile("ldmatrix.sync.aligned.m8n8.x4.shared.b16 {%0,%1,%2,%3}, [%4];"
                 : "=r"(r[0]), "=r"(r[1]), "=r"(r[2]), "=r"(r[3]) : "r"(addr));
}

__device__ __forceinline__ void ldm_x4_t(uint32_t r[4], uint32_t addr) {
    asm volatile("ldmatrix.sync.aligned.m8n8.x4.trans.shared.b16 {%0,%1,%2,%3}, [%4];"
                 : "=r"(r[0]), "=r"(r[1]), "=r"(r[2]), "=r"(r[3]) : "r"(addr));
}

__device__ __forceinline__ void cp16(uint32_t smem, const void* g) {
    asm volatile("cp.async.cg.shared.global [%0], [%1], 16;"
                 :: "r"(smem), "l"(__cvta_generic_to_global(g)) : "memory");
}
#define CP_COMMIT() asm volatile("cp.async.commit_group;" ::: "memory")
#define CP_WAIT0()  asm volatile("cp.async.wait_group 0;" ::: "memory")

// A-fragment (Q) ldmatrix address
__device__ __forceinline__ uint32_t qaddr(uint32_t base, int m0, int kt, int lane) {
    int row  = m0 + (lane & 7) + ((lane >> 3) & 1) * 8;
    int byte = kt * 32 + (lane >> 4) * 16;
    return swaddr(base, row, byte);
}

// B-fragment (K) ldmatrix address
__device__ __forceinline__ uint32_t kaddr(uint32_t base, int nbase, int kbase, int lane) {
    int r = lane & 7;
    int n = nbase + ((lane >> 4) << 3) + r;
    int kcol = kbase + ((lane >> 3) & 1) * 8;
    return swaddr(base, n, kcol * 2);
}

// B-fragment (V, trans) address
__device__ __forceinline__ uint32_t vaddr(uint32_t base, int nbase, int dbase, int lane) {
    int r = lane & 7;
    int n = nbase + ((lane >> 3) & 1) * 8 + r;
    int d = dbase + ((lane >> 4) << 3);
    return swaddr(base, n, d * 2);
}

// ================= precompute: K,V fp32 -> fp16, tile-swizzled ===============
__global__ __launch_bounds__(256)
void conv_kernel(const float* __restrict__ k, const float* __restrict__ v)
{
    size_t idx4 = (size_t)blockIdx.x * blockDim.x + threadIdx.x;
    size_t e = idx4 * 4;
    if (e >= NELEM) return;
    int d      = (int)(e & 63);
    int s      = (int)((e >> 6) & (S_ - 1));
    size_t bh  = e >> 17;
    int jb     = s >> 6;
    int row    = s & 63;
    size_t tb  = ((bh * NT) + jb) * 8192;
    uint32_t o = swoff(row, d * 2);

    float4 kx = *reinterpret_cast<const float4*>(k + e);
    float4 vx = *reinterpret_cast<const float4*>(v + e);

    *reinterpret_cast<uint2*>((char*)g_Kh + tb + o) =
        make_uint2(pack2(__float2half_rn(kx.x), __float2half_rn(kx.y)),
                   pack2(__float2half_rn(kx.z), __float2half_rn(kx.w)));
    *reinterpret_cast<uint2*>((char*)g_Vh + tb + o) =
        make_uint2(pack2(__float2half_rn(vx.x), __float2half_rn(vx.y)),
                   pack2(__float2half_rn(vx.z), __float2half_rn(vx.w)));
}

// ================= main attention kernel =====================================
struct Smem {
    __half Qh[BM][64];      // 8 KB  static
    __half Ql[BM][64];      // 8 KB  static
    __half Kh[2][BN][64];   // 16 KB double
    __half Vr[2][BN][64];   // 16 KB double
};                          // 48 KB -> 3 CTAs/SM

#define OEX_LD 68

__global__ __launch_bounds__(128, 3)
void fa_kernel(const float* __restrict__ q, const float* __restrict__ mask,
               float* __restrict__ out)
{
    __shared__ Smem sm;

    const int bh   = blockIdx.x;
    const int qb   = blockIdx.y;
    const int b    = bh / H_;
    const int tid  = threadIdx.x;
    const int warp = tid >> 5;
    const int lane = tid & 31;
    const int c    = warp & 1;        // kv-col half
    const int r    = warp >> 1;       // q-row half
    const int g    = lane >> 2;
    const int t    = lane & 3;

    const uint32_t qhb = s2u(&sm.Qh[0][0]);
    const uint32_t qlb = s2u(&sm.Ql[0][0]);
    const uint32_t khb[2] = { s2u(&sm.Kh[0][0][0]), s2u(&sm.Kh[1][0][0]) };
    const uint32_t vrb[2] = { s2u(&sm.Vr[0][0][0]), s2u(&sm.Vr[1][0][0]) };

    const int row0 = qb * BM + r * 32;

    const char* gKh = (const char*)g_Kh + (size_t)bh * NT * 8192;
    const char* gVh = (const char*)g_Vh + (size_t)bh * NT * 8192;

    // cp.async one 16 KB tile (Kh,V) into buffer buf
    auto cp_tile = [&](int jb, int buf) {
        size_t tb = (size_t)jb * 8192;
#pragma unroll
        for (int i = 0; i < 4; ++i) {
            uint32_t o = (uint32_t)(tid + i * 128) * 16;
            cp16(khb[buf] + o, gKh + tb + o);
            cp16(vrb[buf] + o, gVh + tb + o);
        }
    };

    cp_tile(0, 0);
    CP_COMMIT();

    // ---- Q -> smem hi/lo fp16 (once, overlaps the first cp.async) ----
    {
        const int ld_row = tid >> 4;
        const int ld_c4  = (tid & 15) * 4;
        const float* qp = q + ((size_t)bh * S_ + qb * BM) * D_;
#pragma unroll
        for (int i = 0; i < 8; ++i) {
            int row = ld_row + i * 8;
            float4 x = *reinterpret_cast<const float4*>(qp + row * D_ + ld_c4);
            __half h0 = __float2half_rn(x.x), h1 = __float2half_rn(x.y);
            __half h2 = __float2half_rn(x.z), h3 = __float2half_rn(x.w);
            __half l0 = __float2half_rn(x.x - __half2float(h0));
            __half l1 = __float2half_rn(x.y - __half2float(h1));
            __half l2 = __float2half_rn(x.z - __half2float(h2));
            __half l3 = __float2half_rn(x.w - __half2float(h3));
            uint2 hv = make_uint2(pack2(h0, h1), pack2(h2, h3));
            uint2 lv = make_uint2(pack2(l0, l1), pack2(l2, l3));
            asm volatile("st.shared.v2.u32 [%0], {%1,%2};"
                         :: "r"(swaddr(qhb, row, ld_c4 * 2)), "r"(hv.x), "r"(hv.y));
            asm volatile("st.shared.v2.u32 [%0], {%1,%2};"
                         :: "r"(swaddr(qlb, row, ld_c4 * 2)), "r"(lv.x), "r"(lv.y));
        }
    }

    float oA[2][8][4];
#pragma unroll
    for (int mt = 0; mt < 2; ++mt)
#pragma unroll
        for (int jd = 0; jd < 8; ++jd)
#pragma unroll
            for (int i = 0; i < 4; ++i) oA[mt][jd][i] = 0.f;

    float m_run[2][2] = { {-1e30f, -1e30f}, {-1e30f, -1e30f} };
    float l_run[2][2] = { {0.f, 0.f}, {0.f, 0.f} };

    const float* mbase = mask + (size_t)b * S_ * S_
                       + (size_t)(row0 + g) * S_ + c * 32 + 2 * t;

    const float L2E = 1.4426950408889634f;

    CP_WAIT0();
    __syncthreads();

    for (int jb = 0; jb < NT; ++jb) {
        const int buf = jb & 1;

        // issue next tile's copies first — overlap with this tile's math
        if (jb + 1 < NT) { cp_tile(jb + 1, buf ^ 1); CP_COMMIT(); }

        float sA[2][4][4];
#pragma unroll
        for (int mt = 0; mt < 2; ++mt)
#pragma unroll
            for (int j8 = 0; j8 < 4; ++j8)
#pragma unroll
                for (int i = 0; i < 4; ++i) sA[mt][j8][i] = 0.f;

        // ---- S = Q K^T : 2-term fp16 split (qh*kh + ql*kh) ----
#pragma unroll
        for (int kt = 0; kt < 4; ++kt) {
            uint32_t ah[2][4], al[2][4], bh0[8];
#pragma unroll
            for (int mt = 0; mt < 2; ++mt) {
                ldm_x4(ah[mt], qaddr(qhb, r * 32 + mt * 16, kt, lane));
                ldm_x4(al[mt], qaddr(qlb, r * 32 + mt * 16, kt, lane));
            }
#pragma unroll
            for (int nb = 0; nb < 2; ++nb)
                ldm_x4(&bh0[nb * 4], kaddr(khb[buf], c * 32 + nb * 16, kt * 16, lane));
#pragma unroll
            for (int mt = 0; mt < 2; ++mt)
#pragma unroll
                for (int j8 = 0; j8 < 4; ++j8) {
                    int off = (j8 >> 1) * 4 + (j8 & 1) * 2;
                    mma16816(sA[mt][j8], ah[mt], bh0[off], bh0[off + 1]);
                    mma16816(sA[mt][j8], al[mt], bh0[off], bh0[off + 1]);
                }
        }

        // ---- additive mask (fp32, L2-resident) ----
        const float* mp = mbase + (size_t)jb * BN;
#pragma unroll
        for (int mt = 0; mt < 2; ++mt)
#pragma unroll
            for (int rr = 0; rr < 2; ++rr) {
                const float* mq = mp + (size_t)(mt * 16 + rr * 8) * S_;
#pragma unroll
                for (int j8 = 0; j8 < 4; ++j8) {
                    float2 mv = *reinterpret_cast<const float2*>(mq + j8 * 8);
                    sA[mt][j8][rr * 2 + 0] += mv.x;
                    sA[mt][j8][rr * 2 + 1] += mv.y;
                }
            }

        // ---- per-warp-local online softmax ----
        uint32_t Pa[2][2][4];
#pragma unroll
        for (int mt = 0; mt < 2; ++mt) {
            float rm0 = -1e30f, rm1 = -1e30f;
#pragma unroll
            for (int j8 = 0; j8 < 4; ++j8) {
                rm0 = fmaxf(rm0, fmaxf(sA[mt][j8][0], sA[mt][j8][1]));
                rm1 = fmaxf(rm1, fmaxf(sA[mt][j8][2], sA[mt][j8][3]));
            }
            rm0 = fmaxf(rm0, __shfl_xor_sync(0xffffffffu, rm0, 1));
            rm0 = fmaxf(rm0, __shfl_xor_sync(0xffffffffu, rm0, 2));
            rm1 = fmaxf(rm1, __shfl_xor_sync(0xffffffffu, rm1, 1));
            rm1 = fmaxf(rm1, __shfl_xor_sync(0xffffffffu, rm1, 2));

            float mn0 = fmaxf(m_run[mt][0], rm0), mn1 = fmaxf(m_run[mt][1], rm1);
            float al0 = ex2f((m_run[mt][0] - mn0) * L2E);
            float al1 = ex2f((m_run[mt][1] - mn1) * L2E);
            m_run[mt][0] = mn0; m_run[mt][1] = mn1;

            float rs0 = 0.f, rs1 = 0.f;
#pragma unroll
            for (int j8 = 0; j8 < 4; ++j8) {
                float p0 = ex2f((sA[mt][j8][0] - mn0) * L2E);
                float p1 = ex2f((sA[mt][j8][1] - mn0) * L2E);
                float p2 = ex2f((sA[mt][j8][2] - mn1) * L2E);
                float p3 = ex2f((sA[mt][j8][3] - mn1) * L2E);
                rs0 += p0 + p1;
                rs1 += p2 + p3;
                Pa[mt][j8 >> 1][(j8 & 1) * 2 + 0] = pack2(__float2half_rn(p0), __float2half_rn(p1));
                Pa[mt][j8 >> 1][(j8 & 1) * 2 + 1] = pack2(__float2half_rn(p2), __float2half_rn(p3));
            }
            rs0 += __shfl_xor_sync(0xffffffffu, rs0, 1);
            rs0 += __shfl_xor_sync(0xffffffffu, rs0, 2);
            rs1 += __shfl_xor_sync(0xffffffffu, rs1, 1);
            rs1 += __shfl_xor_sync(0xffffffffu, rs1, 2);
            l_run[mt][0] = l_run[mt][0] * al0 + rs0;
            l_run[mt][1] = l_run[mt][1] * al1 + rs1;

#pragma unroll
            for (int jd = 0; jd < 8; ++jd) {
                oA[mt][jd][0] *= al0; oA[mt][jd][1] *= al0;
                oA[mt][jd][2] *= al1; oA[mt][jd][3] *= al1;
            }
        }

        // ---- O_c += P_c V_c ----
#pragma unroll
        for (int ks = 0; ks < 2; ++ks) {
            uint32_t bv[16];
#pragma unroll
            for (int db = 0; db < 4; ++db)
                ldm_x4_t(&bv[db * 4], vaddr(vrb[buf], c * 32 + ks * 16, db * 16, lane));
#pragma unroll
            for (int mt = 0; mt < 2; ++mt)
#pragma unroll
                for (int jd = 0; jd < 8; ++jd) {
                    int off = (jd >> 1) * 4 + (jd & 1) * 2;
                    mma16816(oA[mt][jd], Pa[mt][ks], bv[off], bv[off + 1]);
                }
        }

        CP_WAIT0();
        __syncthreads();
    }

    // ---- epilogue: merge the two c-halves ----
    float* Oex = reinterpret_cast<float*>(&sm);          // [64][OEX_LD]
    float* Mex = Oex + 64 * OEX_LD;
    float* Lex = Mex + 64;

    if (c == 1) {
#pragma unroll
        for (int mt = 0; mt < 2; ++mt) {
#pragma unroll
            for (int rr = 0; rr < 2; ++rr) {
                int row_l = r * 32 + mt * 16 + rr * 8 + g;
#pragma unroll
                for (int jd = 0; jd < 8; ++jd) {
                    Oex[row_l * OEX_LD + jd * 8 + 2 * t]     = oA[mt][jd][rr * 2 + 0];
                    Oex[row_l * OEX_LD + jd * 8 + 2 * t + 1] = oA[mt][jd][rr * 2 + 1];
                }
            }
            if (t == 0) {
                int rl0 = r * 32 + mt * 16 + g;
                Mex[rl0]     = m_run[mt][0];  Lex[rl0]     = l_run[mt][0];
                Mex[rl0 + 8] = m_run[mt][1];  Lex[rl0 + 8] = l_run[mt][1];
            }
        }
    }
    __syncthreads();

    if (c == 0) {
#pragma unroll
        for (int mt = 0; mt < 2; ++mt) {
#pragma unroll
            for (int rr = 0; rr < 2; ++rr) {
                int row_l = r * 32 + mt * 16 + rr * 8 + g;
                float m0 = m_run[mt][rr], l0 = l_run[mt][rr];
                float m1 = Mex[row_l],    l1 = Lex[row_l];
                float m  = fmaxf(m0, m1);
                float s0 = ex2f((m0 - m) * L2E);
                float s1 = ex2f((m1 - m) * L2E);
                float inv = 1.f / (l0 * s0 + l1 * s1);
                float a0 = s0 * inv, a1 = s1 * inv;

                float* op = out + ((size_t)bh * S_ + qb * BM + row_l) * D_;
#pragma unroll
                for (int jd = 0; jd < 8; ++jd) {
                    float2 w;
                    w.x = oA[mt][jd][rr * 2 + 0] * a0 + Oex[row_l * OEX_LD + jd * 8 + 2 * t] * a1;
                    w.y = oA[mt][jd][rr * 2 + 1] * a0 + Oex[row_l * OEX_LD + jd * 8 + 2 * t + 1] * a1;
                    *reinterpret_cast<float2*>(op + jd * 8 + 2 * t) = w;
                }
            }
        }
    }
}

extern "C" void kernel_launch(void* const* d_in, const int* in_sizes, int n_in,
                              void* d_out, int out_size) {
    (void)in_sizes; (void)n_in; (void)out_size;
    const float* q    = (const float*)d_in[0];
    const float* k    = (const float*)d_in[1];
    const float* v    = (const float*)d_in[2];
    const float* mask = (const float*)d_in[3];

    conv_kernel<<<NELEM / 4 / 256, 256>>>(k, v);
    dim3 grid(B_ * H_, S_ / BM);
    fa_kernel<<<grid, 128>>>(q, mask, (float*)d_out);
}